// round 7
// baseline (speedup 1.0000x reference)
#include <cuda_runtime.h>
#include <cuda_bf16.h>

// HashingDiscretizer (R6): 4 elems/thread vectorized hot kernel + streaming
// cache hints + slim detect kernel.
//
// calibrated (key in feature table == arange(F)):
//   bin = lower_bound(bin_vals[key*63..+63], val) in [0,63]
//   out_key = (((u32)key * GOLDEN + bin) * GOLDEN) & (2^22-1), out_val = 1
// else: out_key = key & (2^22-1), out_val = val
// Output float[2*nnz] = [out_keys ; out_vals] (exact in f32).
//
// Bin search structure per feature (built per launch):
//   T[0..7]  = {S31,S15,S47,S7,S23,S39,S55,+INF}  (top 3 tree levels, 1 sector)
//   T[8..71] = S[0..62] padded +INF               (8 aligned 32B chunks)
// Hot path per elem: 2x LDG.128 (top sector) -> 3 branchless levels -> p ->
// 2x LDG.128 (chunk sector) -> bin = 8p + sum(chunk < v).

#define NBIN 63
#define MAX_F 8192
#define OUT_MASK 0x3FFFFFu
#define GOLDEN 0x9E3779B9u

__device__ float4 g_tree[MAX_F * 18];  // 72 floats (18 float4) per feature
__device__ int g_k64;     // 1 if keys buffer is int64
__device__ int g_f64;     // 1 if feature_ids buffer is int64
__device__ int g_arange;  // 1 if feature_ids == arange(F)

__global__ void detect_kernel(const unsigned* __restrict__ keys,
                              const unsigned* __restrict__ fid,
                              int nnz, int F) {
    __shared__ int s_k32, s_f32, s_bad;
    if (threadIdx.x == 0) { s_k32 = 0; s_f32 = 0; s_bad = 0; }
    __syncthreads();
    // int64 little-endian small nonneg values => odd u32 words all zero.
    int lk = 0, lf = 0;
    int nk = min(nnz, 1024);
    for (int i = threadIdx.x; i < nk; i += blockDim.x)
        if (keys[2 * i + 1] != 0u) lk = 1;
    int nf = min(F, 1024);
    for (int i = threadIdx.x; i < nf; i += blockDim.x)
        if (fid[2 * i + 1] != 0u) lf = 1;
    if (lk) atomicOr(&s_k32, 1);
    if (lf) atomicOr(&s_f32, 1);
    __syncthreads();
    int f64 = !s_f32;
    int bad = 0;
    if (f64) {
        const long long* p = (const long long*)fid;
        for (int i = threadIdx.x; i < F; i += blockDim.x)
            if (p[i] != (long long)i) bad = 1;
    } else {
        const int* p = (const int*)fid;
        for (int i = threadIdx.x; i < F; i += blockDim.x)
            if (p[i] != i) bad = 1;
    }
    if (bad) atomicOr(&s_bad, 1);
    __syncthreads();
    if (threadIdx.x == 0) {
        g_k64 = !s_k32;
        g_f64 = f64;
        g_arange = !s_bad;
    }
}

__global__ void build_tree_kernel(const float* __restrict__ bin_vals, int F) {
    int f = blockIdx.x;
    if (f >= F) return;
    int t = threadIdx.x;  // 64 threads
    const float* S = bin_vals + (long long)f * NBIN;
    float* T = reinterpret_cast<float*>(g_tree) + (long long)f * 72;
    float inf = __int_as_float(0x7f800000);
    T[8 + t] = (t < NBIN) ? S[t] : inf;  // padded sorted row
    if (t == 0) {
        T[0] = S[31]; T[1] = S[15]; T[2] = S[47]; T[3] = S[7];
        T[4] = S[23]; T[5] = S[39]; T[6] = S[55]; T[7] = inf;
    }
}

// One calibrated-path tree descent (key already known < F).
__device__ __forceinline__ void descend(int fx, float v, long long key,
                                        unsigned& okey, float& oval) {
    const float4* base = g_tree + fx * 18;
    float4 t0 = __ldg(base);      // {S31, S15, S47, S7}
    float4 t1 = __ldg(base + 1);  // {S23, S39, S55, INF}
    int b0 = t0.x < v;
    float k1 = b0 ? t0.z : t0.y;
    int b1 = k1 < v;
    float kA = b1 ? t1.x : t0.w;
    float kB = b1 ? t1.z : t1.y;
    float k2 = b0 ? kB : kA;
    int b2 = k2 < v;
    int p = (b0 << 2) | (b1 << 1) | b2;
    float4 c0 = __ldg(base + 2 + 2 * p);
    float4 c1 = __ldg(base + 3 + 2 * p);
    int bin = (p << 3)
            + (c0.x < v) + (c0.y < v) + (c0.z < v) + (c0.w < v)
            + (c1.x < v) + (c1.y < v) + (c1.z < v) + (c1.w < v);
    unsigned h = ((unsigned)(unsigned long long)key * GOLDEN
                  + (unsigned)bin) * GOLDEN;
    okey = h & OUT_MASK;
    oval = 1.0f;
}

__device__ __forceinline__ void process(long long key, float v, int F,
                                        unsigned& okey, float& oval) {
    if ((unsigned long long)key < (unsigned long long)F) {
        descend((int)key, v, key, okey, oval);
    } else {
        okey = (unsigned)(unsigned long long)key & OUT_MASK;
        oval = v;
    }
}

// Hot kernel: 4 elements per thread, vectorized IO, streaming cache hints.
__global__ __launch_bounds__(256)
void hot_kernel(const void* __restrict__ keys_,
                const float* __restrict__ vals,
                float* __restrict__ out,
                int nnz, int F) {
    int t = blockIdx.x * blockDim.x + threadIdx.x;
    int base = t * 4;
    if (base >= nnz) return;

    long long k[4];
    float v[4];
    bool full = (base + 4 <= nnz) && ((base & 3) == 0);

    if (full) {
        if (g_k64) {
            const longlong2* kp = (const longlong2*)keys_ + t * 2;
            longlong2 a = __ldcs(kp), b = __ldcs(kp + 1);
            k[0] = a.x; k[1] = a.y; k[2] = b.x; k[3] = b.y;
        } else {
            int4 a = __ldcs((const int4*)keys_ + t);
            k[0] = a.x; k[1] = a.y; k[2] = a.z; k[3] = a.w;
        }
        float4 vv = __ldcs((const float4*)vals + t);
        v[0] = vv.x; v[1] = vv.y; v[2] = vv.z; v[3] = vv.w;

        unsigned ok[4]; float ov[4];
#pragma unroll
        for (int j = 0; j < 4; j++) process(k[j], v[j], F, ok[j], ov[j]);

        float4 fo = make_float4((float)ok[0], (float)ok[1],
                                (float)ok[2], (float)ok[3]);
        float4 vo = make_float4(ov[0], ov[1], ov[2], ov[3]);
        __stcs((float4*)(out + base), fo);
        __stcs((float4*)(out + nnz + base), vo);
    } else {
        for (int j = 0; j < 4 && base + j < nnz; j++) {
            long long key = g_k64 ? ((const long long*)keys_)[base + j]
                                  : (long long)((const int*)keys_)[base + j];
            float vj = vals[base + j];
            unsigned ok; float ov;
            process(key, vj, F, ok, ov);
            out[base + j] = (float)ok;
            out[nnz + base + j] = ov;
        }
    }
}

// Generic fallback (feature_ids not arange): scalar searchsorted path.
__global__ __launch_bounds__(256)
void fallback_kernel(const void* __restrict__ keys_,
                     const float* __restrict__ vals,
                     const void* __restrict__ fid_,
                     float* __restrict__ out,
                     int nnz, int F) {
    int i = blockIdx.x * blockDim.x + threadIdx.x;
    if (i >= nnz) return;
    if (g_arange) return;  // hot kernel handled it

    long long key = g_k64 ? ((const long long*)keys_)[i]
                          : (long long)((const int*)keys_)[i];
    float v = vals[i];

    int lo = 0, hi = F, fx;
    bool cal;
    if (g_f64) {
        const long long* fid = (const long long*)fid_;
        while (lo < hi) {
            int mid = (lo + hi) >> 1;
            if (__ldg(fid + mid) < key) lo = mid + 1; else hi = mid;
        }
        fx = min(lo, F - 1);
        cal = (__ldg(fid + fx) == key);
    } else {
        const int* fid = (const int*)fid_;
        int k32 = (int)key;
        while (lo < hi) {
            int mid = (lo + hi) >> 1;
            if (__ldg(fid + mid) < k32) lo = mid + 1; else hi = mid;
        }
        fx = min(lo, F - 1);
        cal = (__ldg(fid + fx) == k32);
    }

    unsigned ok; float ov;
    if (cal) descend(fx, v, key, ok, ov);
    else { ok = (unsigned)(unsigned long long)key & OUT_MASK; ov = v; }
    out[i] = (float)ok;
    out[nnz + i] = ov;
}

// Hot kernel guard: if not arange, skip (fallback covers it).
__global__ __launch_bounds__(256)
void hot_dispatch_stub() {}

extern "C" void kernel_launch(void* const* d_in, const int* in_sizes, int n_in,
                              void* d_out, int out_size) {
    const void* keys  = d_in[0];
    const float* vals = (const float*)d_in[1];
    const void* fid   = d_in[2];
    const float* bins = (const float*)d_in[3];
    int nnz = in_sizes[0];
    int F   = in_sizes[2];

    detect_kernel<<<1, 1024>>>((const unsigned*)keys, (const unsigned*)fid,
                               nnz, F);
    build_tree_kernel<<<F, 64>>>(bins, F);

    const int threads = 256;
    int blocks4 = (nnz + threads * 4 - 1) / (threads * 4);
    hot_kernel<<<blocks4, threads>>>(keys, vals, (float*)d_out, nnz, F);
    // Fallback only writes if g_arange == 0; in practice it exits immediately.
    int blocks1 = (nnz + threads - 1) / threads;
    fallback_kernel<<<blocks1, threads>>>(keys, vals, fid, (float*)d_out,
                                          nnz, F);
}

// round 8
// speedup vs baseline: 1.2220x; 1.2220x over previous
#include <cuda_runtime.h>
#include <cuda_bf16.h>

// HashingDiscretizer (R7): single hot kernel (fallback folded in as a uniform
// branch), 4 elems/thread vectorized IO, streaming cache hints, slim detect.
//
// calibrated (key in feature table == arange(F)):
//   bin = lower_bound(bin_vals[key*63..+63], val) in [0,63]
//   out_key = (((u32)key * GOLDEN + bin) * GOLDEN) & (2^22-1), out_val = 1
// else: out_key = key & (2^22-1), out_val = val
// Output float[2*nnz] = [out_keys ; out_vals] (exact in f32).
//
// Bin search structure per feature (built per launch):
//   T[0..7]  = {S31,S15,S47,S7,S23,S39,S55,+INF}  (top 3 tree levels, 1 sector)
//   T[8..71] = S[0..62] padded +INF               (8 aligned 32B chunks)
// Hot path per elem: 2x LDG.128 (top sector) -> 3 branchless levels -> p ->
// 2x LDG.128 (chunk sector) -> bin = 8p + sum(chunk < v).

#define NBIN 63
#define MAX_F 8192
#define OUT_MASK 0x3FFFFFu
#define GOLDEN 0x9E3779B9u

__device__ float4 g_tree[MAX_F * 18];  // 72 floats (18 float4) per feature
__device__ int g_k64;     // 1 if keys buffer is int64
__device__ int g_f64;     // 1 if feature_ids buffer is int64
__device__ int g_arange;  // 1 if feature_ids == arange(F)

__global__ void detect_kernel(const unsigned* __restrict__ keys,
                              const unsigned* __restrict__ fid,
                              int nnz, int F) {
    __shared__ int s_k32, s_f32, s_bad;
    if (threadIdx.x == 0) { s_k32 = 0; s_f32 = 0; s_bad = 0; }
    __syncthreads();
    // int64 little-endian small nonneg values => odd u32 words all zero.
    int lk = 0, lf = 0;
    int nk = min(nnz, 1024);
    for (int i = threadIdx.x; i < nk; i += blockDim.x)
        if (keys[2 * i + 1] != 0u) lk = 1;
    int nf = min(F, 1024);
    for (int i = threadIdx.x; i < nf; i += blockDim.x)
        if (fid[2 * i + 1] != 0u) lf = 1;
    if (lk) atomicOr(&s_k32, 1);
    if (lf) atomicOr(&s_f32, 1);
    __syncthreads();
    int f64 = !s_f32;
    int bad = 0;
    if (f64) {
        const long long* p = (const long long*)fid;
        for (int i = threadIdx.x; i < F; i += blockDim.x)
            if (p[i] != (long long)i) bad = 1;
    } else {
        const int* p = (const int*)fid;
        for (int i = threadIdx.x; i < F; i += blockDim.x)
            if (p[i] != i) bad = 1;
    }
    if (bad) atomicOr(&s_bad, 1);
    __syncthreads();
    if (threadIdx.x == 0) {
        g_k64 = !s_k32;
        g_f64 = f64;
        g_arange = !s_bad;
    }
}

__global__ void build_tree_kernel(const float* __restrict__ bin_vals, int F) {
    int f = blockIdx.x;
    if (f >= F) return;
    int t = threadIdx.x;  // 64 threads
    const float* S = bin_vals + (long long)f * NBIN;
    float* T = reinterpret_cast<float*>(g_tree) + (long long)f * 72;
    float inf = __int_as_float(0x7f800000);
    T[8 + t] = (t < NBIN) ? S[t] : inf;  // padded sorted row
    if (t == 0) {
        T[0] = S[31]; T[1] = S[15]; T[2] = S[47]; T[3] = S[7];
        T[4] = S[23]; T[5] = S[39]; T[6] = S[55]; T[7] = inf;
    }
}

// One calibrated-path tree descent.
__device__ __forceinline__ void descend(int fx, float v, long long key,
                                        unsigned& okey, float& oval) {
    const float4* base = g_tree + fx * 18;
    float4 t0 = __ldg(base);      // {S31, S15, S47, S7}
    float4 t1 = __ldg(base + 1);  // {S23, S39, S55, INF}
    int b0 = t0.x < v;
    float k1 = b0 ? t0.z : t0.y;
    int b1 = k1 < v;
    float kA = b1 ? t1.x : t0.w;
    float kB = b1 ? t1.z : t1.y;
    float k2 = b0 ? kB : kA;
    int b2 = k2 < v;
    int p = (b0 << 2) | (b1 << 1) | b2;
    float4 c0 = __ldg(base + 2 + 2 * p);
    float4 c1 = __ldg(base + 3 + 2 * p);
    int bin = (p << 3)
            + (c0.x < v) + (c0.y < v) + (c0.z < v) + (c0.w < v)
            + (c1.x < v) + (c1.y < v) + (c1.z < v) + (c1.w < v);
    unsigned h = ((unsigned)(unsigned long long)key * GOLDEN
                  + (unsigned)bin) * GOLDEN;
    okey = h & OUT_MASK;
    oval = 1.0f;
}

// Fast path: feature table is arange(F).
__device__ __forceinline__ void process_fast(long long key, float v, int F,
                                             unsigned& okey, float& oval) {
    if ((unsigned long long)key < (unsigned long long)F) {
        descend((int)key, v, key, okey, oval);
    } else {
        okey = (unsigned)(unsigned long long)key & OUT_MASK;
        oval = v;
    }
}

// Generic path: searchsorted(feature_ids, key, 'left').
__device__ __forceinline__ void process_generic(long long key, float v,
                                                const void* fid_, int F,
                                                unsigned& okey, float& oval) {
    int lo = 0, hi = F, fx;
    bool cal;
    if (g_f64) {
        const long long* fid = (const long long*)fid_;
        while (lo < hi) {
            int mid = (lo + hi) >> 1;
            if (__ldg(fid + mid) < key) lo = mid + 1; else hi = mid;
        }
        fx = min(lo, F - 1);
        cal = (__ldg(fid + fx) == key);
    } else {
        const int* fid = (const int*)fid_;
        int k32 = (int)key;
        while (lo < hi) {
            int mid = (lo + hi) >> 1;
            if (__ldg(fid + mid) < k32) lo = mid + 1; else hi = mid;
        }
        fx = min(lo, F - 1);
        cal = (__ldg(fid + fx) == k32);
    }
    if (cal) descend(fx, v, key, okey, oval);
    else {
        okey = (unsigned)(unsigned long long)key & OUT_MASK;
        oval = v;
    }
}

// Hot kernel: 4 elements per thread, vectorized IO, streaming cache hints.
// Generic fallback handled by a uniform branch (same value for all threads).
__global__ __launch_bounds__(256)
void hot_kernel(const void* __restrict__ keys_,
                const float* __restrict__ vals,
                const void* __restrict__ fid_,
                float* __restrict__ out,
                int nnz, int F) {
    int t = blockIdx.x * blockDim.x + threadIdx.x;
    int base = t * 4;
    if (base >= nnz) return;

    int arange = g_arange;
    long long k[4];
    float v[4];
    bool full = (base + 4 <= nnz);

    if (full) {
        if (g_k64) {
            const longlong2* kp = (const longlong2*)keys_ + t * 2;
            longlong2 a = __ldcs(kp), b = __ldcs(kp + 1);
            k[0] = a.x; k[1] = a.y; k[2] = b.x; k[3] = b.y;
        } else {
            int4 a = __ldcs((const int4*)keys_ + t);
            k[0] = a.x; k[1] = a.y; k[2] = a.z; k[3] = a.w;
        }
        float4 vv = __ldcs((const float4*)vals + t);
        v[0] = vv.x; v[1] = vv.y; v[2] = vv.z; v[3] = vv.w;

        unsigned ok[4]; float ov[4];
        if (arange) {
#pragma unroll
            for (int j = 0; j < 4; j++)
                process_fast(k[j], v[j], F, ok[j], ov[j]);
        } else {
#pragma unroll
            for (int j = 0; j < 4; j++)
                process_generic(k[j], v[j], fid_, F, ok[j], ov[j]);
        }

        float4 fo = make_float4((float)ok[0], (float)ok[1],
                                (float)ok[2], (float)ok[3]);
        float4 vo = make_float4(ov[0], ov[1], ov[2], ov[3]);
        __stcs((float4*)(out + base), fo);
        __stcs((float4*)(out + nnz + base), vo);
    } else {
        for (int j = 0; j < 4 && base + j < nnz; j++) {
            long long key = g_k64 ? ((const long long*)keys_)[base + j]
                                  : (long long)((const int*)keys_)[base + j];
            float vj = vals[base + j];
            unsigned ok; float ov;
            if (arange) process_fast(key, vj, F, ok, ov);
            else        process_generic(key, vj, fid_, F, ok, ov);
            out[base + j] = (float)ok;
            out[nnz + base + j] = ov;
        }
    }
}

extern "C" void kernel_launch(void* const* d_in, const int* in_sizes, int n_in,
                              void* d_out, int out_size) {
    const void* keys  = d_in[0];
    const float* vals = (const float*)d_in[1];
    const void* fid   = d_in[2];
    const float* bins = (const float*)d_in[3];
    int nnz = in_sizes[0];
    int F   = in_sizes[2];

    detect_kernel<<<1, 1024>>>((const unsigned*)keys, (const unsigned*)fid,
                               nnz, F);
    build_tree_kernel<<<F, 64>>>(bins, F);

    const int threads = 256;
    int blocks4 = (nnz + threads * 4 - 1) / (threads * 4);
    hot_kernel<<<blocks4, threads>>>(keys, vals, fid, (float*)d_out, nnz, F);
}

// round 9
// speedup vs baseline: 1.2555x; 1.0274x over previous
#include <cuda_runtime.h>
#include <cuda_bf16.h>

// HashingDiscretizer (R8): detect fused into build kernel (detect's
// single-block latency hides under the 2048-block tree build), then one hot
// kernel: 4 elems/thread vectorized IO, streaming cache hints.
//
// calibrated (key in feature table == arange(F)):
//   bin = lower_bound(bin_vals[key*63..+63], val) in [0,63]
//   out_key = (((u32)key * GOLDEN + bin) * GOLDEN) & (2^22-1), out_val = 1
// else: out_key = key & (2^22-1), out_val = val
// Output float[2*nnz] = [out_keys ; out_vals] (exact in f32).
//
// Bin search structure per feature (built per launch):
//   T[0..7]  = {S31,S15,S47,S7,S23,S39,S55,+INF}  (top 3 tree levels, 1 sector)
//   T[8..71] = S[0..62] padded +INF               (8 aligned 32B chunks)
// Hot path per elem: 2x LDG.128 (top sector) -> 3 branchless levels -> p ->
// 2x LDG.128 (chunk sector) -> bin = 8p + sum(chunk < v). 2 sectors/elem.

#define NBIN 63
#define MAX_F 8192
#define OUT_MASK 0x3FFFFFu
#define GOLDEN 0x9E3779B9u
#define FEAT_PER_BLOCK 4

__device__ float4 g_tree[MAX_F * 18];  // 72 floats (18 float4) per feature
__device__ int g_k64;     // 1 if keys buffer is int64
__device__ int g_f64;     // 1 if feature_ids buffer is int64
__device__ int g_arange;  // 1 if feature_ids == arange(F)

// Fused prep kernel. Blocks [0, nb_build) build the per-feature search trees;
// block nb_build does dtype sniffing + arange verification (its ~9us of
// single-block latency hides under the build wave).
__global__ __launch_bounds__(256)
void prep_kernel(const float* __restrict__ bin_vals,
                 const unsigned* __restrict__ keys,
                 const unsigned* __restrict__ fid,
                 int nnz, int F, int nb_build) {
    if ((int)blockIdx.x < nb_build) {
        // ---- tree build: FEAT_PER_BLOCK features per 256-thread block ----
        int t = threadIdx.x;
        int f = blockIdx.x * FEAT_PER_BLOCK + (t >> 6);  // 64 threads/feature
        int lane = t & 63;
        if (f >= F) return;
        const float* S = bin_vals + (long long)f * NBIN;
        float* T = reinterpret_cast<float*>(g_tree) + (long long)f * 72;
        float inf = __int_as_float(0x7f800000);
        T[8 + lane] = (lane < NBIN) ? S[lane] : inf;  // padded sorted row
        if (lane == 0) {
            T[0] = S[31]; T[1] = S[15]; T[2] = S[47]; T[3] = S[7];
            T[4] = S[23]; T[5] = S[39]; T[6] = S[55]; T[7] = inf;
        }
        return;
    }

    // ---- detection block ----
    __shared__ int s_k32, s_f32, s_bad;
    if (threadIdx.x == 0) { s_k32 = 0; s_f32 = 0; s_bad = 0; }
    __syncthreads();
    // int64 little-endian small nonneg values => odd u32 words all zero;
    // int32 random in-range values => odd words mostly nonzero.
    int lk = 0, lf = 0;
    int nk = min(nnz, 1024);
    for (int i = threadIdx.x; i < nk; i += blockDim.x)
        if (keys[2 * i + 1] != 0u) lk = 1;
    int nf = min(F, 1024);
    for (int i = threadIdx.x; i < nf; i += blockDim.x)
        if (fid[2 * i + 1] != 0u) lf = 1;
    if (lk) atomicOr(&s_k32, 1);
    if (lf) atomicOr(&s_f32, 1);
    __syncthreads();
    int f64 = !s_f32;
    int bad = 0;
    if (f64) {
        const long long* p = (const long long*)fid;
        for (int i = threadIdx.x; i < F; i += blockDim.x)
            if (p[i] != (long long)i) bad = 1;
    } else {
        const int* p = (const int*)fid;
        for (int i = threadIdx.x; i < F; i += blockDim.x)
            if (p[i] != i) bad = 1;
    }
    if (bad) atomicOr(&s_bad, 1);
    __syncthreads();
    if (threadIdx.x == 0) {
        g_k64 = !s_k32;
        g_f64 = f64;
        g_arange = !s_bad;
    }
}

// One calibrated-path tree descent.
__device__ __forceinline__ void descend(int fx, float v, long long key,
                                        unsigned& okey, float& oval) {
    const float4* base = g_tree + fx * 18;
    float4 t0 = __ldg(base);      // {S31, S15, S47, S7}
    float4 t1 = __ldg(base + 1);  // {S23, S39, S55, INF}
    int b0 = t0.x < v;
    float k1 = b0 ? t0.z : t0.y;
    int b1 = k1 < v;
    float kA = b1 ? t1.x : t0.w;
    float kB = b1 ? t1.z : t1.y;
    float k2 = b0 ? kB : kA;
    int b2 = k2 < v;
    int p = (b0 << 2) | (b1 << 1) | b2;
    float4 c0 = __ldg(base + 2 + 2 * p);
    float4 c1 = __ldg(base + 3 + 2 * p);
    int bin = (p << 3)
            + (c0.x < v) + (c0.y < v) + (c0.z < v) + (c0.w < v)
            + (c1.x < v) + (c1.y < v) + (c1.z < v) + (c1.w < v);
    unsigned h = ((unsigned)(unsigned long long)key * GOLDEN
                  + (unsigned)bin) * GOLDEN;
    okey = h & OUT_MASK;
    oval = 1.0f;
}

// Fast path: feature table is arange(F).
__device__ __forceinline__ void process_fast(long long key, float v, int F,
                                             unsigned& okey, float& oval) {
    if ((unsigned long long)key < (unsigned long long)F) {
        descend((int)key, v, key, okey, oval);
    } else {
        okey = (unsigned)(unsigned long long)key & OUT_MASK;
        oval = v;
    }
}

// Generic path: searchsorted(feature_ids, key, 'left').
__device__ __forceinline__ void process_generic(long long key, float v,
                                                const void* fid_, int F,
                                                unsigned& okey, float& oval) {
    int lo = 0, hi = F, fx;
    bool cal;
    if (g_f64) {
        const long long* fid = (const long long*)fid_;
        while (lo < hi) {
            int mid = (lo + hi) >> 1;
            if (__ldg(fid + mid) < key) lo = mid + 1; else hi = mid;
        }
        fx = min(lo, F - 1);
        cal = (__ldg(fid + fx) == key);
    } else {
        const int* fid = (const int*)fid_;
        int k32 = (int)key;
        while (lo < hi) {
            int mid = (lo + hi) >> 1;
            if (__ldg(fid + mid) < k32) lo = mid + 1; else hi = mid;
        }
        fx = min(lo, F - 1);
        cal = (__ldg(fid + fx) == k32);
    }
    if (cal) descend(fx, v, key, okey, oval);
    else {
        okey = (unsigned)(unsigned long long)key & OUT_MASK;
        oval = v;
    }
}

// Hot kernel: 4 elements per thread, vectorized IO, streaming cache hints.
// Generic fallback handled by a uniform branch (same value for all threads).
__global__ __launch_bounds__(256)
void hot_kernel(const void* __restrict__ keys_,
                const float* __restrict__ vals,
                const void* __restrict__ fid_,
                float* __restrict__ out,
                int nnz, int F) {
    int t = blockIdx.x * blockDim.x + threadIdx.x;
    int base = t * 4;
    if (base >= nnz) return;

    int arange = g_arange;
    long long k[4];
    float v[4];
    bool full = (base + 4 <= nnz);

    if (full) {
        if (g_k64) {
            const longlong2* kp = (const longlong2*)keys_ + t * 2;
            longlong2 a = __ldcs(kp), b = __ldcs(kp + 1);
            k[0] = a.x; k[1] = a.y; k[2] = b.x; k[3] = b.y;
        } else {
            int4 a = __ldcs((const int4*)keys_ + t);
            k[0] = a.x; k[1] = a.y; k[2] = a.z; k[3] = a.w;
        }
        float4 vv = __ldcs((const float4*)vals + t);
        v[0] = vv.x; v[1] = vv.y; v[2] = vv.z; v[3] = vv.w;

        unsigned ok[4]; float ov[4];
        if (arange) {
#pragma unroll
            for (int j = 0; j < 4; j++)
                process_fast(k[j], v[j], F, ok[j], ov[j]);
        } else {
#pragma unroll
            for (int j = 0; j < 4; j++)
                process_generic(k[j], v[j], fid_, F, ok[j], ov[j]);
        }

        float4 fo = make_float4((float)ok[0], (float)ok[1],
                                (float)ok[2], (float)ok[3]);
        float4 vo = make_float4(ov[0], ov[1], ov[2], ov[3]);
        __stcs((float4*)(out + base), fo);
        __stcs((float4*)(out + nnz + base), vo);
    } else {
        for (int j = 0; j < 4 && base + j < nnz; j++) {
            long long key = g_k64 ? ((const long long*)keys_)[base + j]
                                  : (long long)((const int*)keys_)[base + j];
            float vj = vals[base + j];
            unsigned ok; float ov;
            if (arange) process_fast(key, vj, F, ok, ov);
            else        process_generic(key, vj, fid_, F, ok, ov);
            out[base + j] = (float)ok;
            out[nnz + base + j] = ov;
        }
    }
}

extern "C" void kernel_launch(void* const* d_in, const int* in_sizes, int n_in,
                              void* d_out, int out_size) {
    const void* keys  = d_in[0];
    const float* vals = (const float*)d_in[1];
    const void* fid   = d_in[2];
    const float* bins = (const float*)d_in[3];
    int nnz = in_sizes[0];
    int F   = in_sizes[2];

    int nb_build = (F + FEAT_PER_BLOCK - 1) / FEAT_PER_BLOCK;  // 2048
    prep_kernel<<<nb_build + 1, 256>>>(bins, (const unsigned*)keys,
                                       (const unsigned*)fid, nnz, F, nb_build);

    const int threads = 256;
    int blocks4 = (nnz + threads * 4 - 1) / (threads * 4);
    hot_kernel<<<blocks4, threads>>>(keys, vals, fid, (float*)d_out, nnz, F);
}

// round 10
// speedup vs baseline: 1.2926x; 1.0296x over previous
#include <cuda_runtime.h>
#include <cuda_bf16.h>

// HashingDiscretizer (R10): pivot descent moved to shared memory.
//
// calibrated (key in feature table == arange(F)):
//   bin = lower_bound(bin_vals[key*63..+63], val) in [0,63]
//   out_key = (((u32)key * GOLDEN + bin) * GOLDEN) & (2^22-1), out_val = 1
// else: out_key = key & (2^22-1), out_val = val
// Output float[2*nnz] = [out_keys ; out_vals] (exact in f32).
//
// Structure (built per launch by prep kernel; detect block fused in):
//   g_piv[7][F]  pivot SoA {S31 | S15,S47 | S7,S23,S39,S55}  (224KB)
//   g_row[F][64] sorted rows padded with +INF (8 aligned 32B chunks/feature)
// Hot kernel: persistent blocks stage g_piv into 224KB smem once, then per
// element: 3 scalar LDS (branchless 3-level descent) -> chunk p ->
// 2x LDG.128 (32B chunk) -> bin = 8p + sum(chunk < v).
// Gather wavefronts: 2/elem (was 4/elem in R9; L1tex was the 83%-SOL pipe).

#define NBIN 63
#define MAX_F 8192
#define OUT_MASK 0x3FFFFFu
#define GOLDEN 0x9E3779B9u
#define FEAT_PER_BLOCK 4
#define PIV_FLOATS (7 * MAX_F)
#define SMEM_BYTES (PIV_FLOATS * 4)  // 229376

__device__ float g_piv[PIV_FLOATS];   // [l][f] SoA
__device__ float4 g_row[MAX_F * 16];  // 64 floats per feature, +INF padded
__device__ int g_k64;     // 1 if keys buffer is int64
__device__ int g_f64;     // 1 if feature_ids buffer is int64
__device__ int g_arange;  // 1 if feature_ids == arange(F)

// Fused prep: blocks [0, nb_build) build rows+pivots; block nb_build does
// dtype sniff + arange verification (latency hidden under the build wave).
__global__ __launch_bounds__(256)
void prep_kernel(const float* __restrict__ bin_vals,
                 const unsigned* __restrict__ keys,
                 const unsigned* __restrict__ fid,
                 int nnz, int F, int nb_build) {
    if ((int)blockIdx.x < nb_build) {
        int t = threadIdx.x;
        int f = blockIdx.x * FEAT_PER_BLOCK + (t >> 6);  // 64 threads/feature
        int lane = t & 63;
        if (f >= F) return;
        const float* S = bin_vals + (long long)f * NBIN;
        float* R = reinterpret_cast<float*>(g_row) + (long long)f * 64;
        float inf = __int_as_float(0x7f800000);
        R[lane] = (lane < NBIN) ? S[lane] : inf;  // padded sorted row
        if (lane == 0) {
            g_piv[0 * MAX_F + f] = S[31];
            g_piv[1 * MAX_F + f] = S[15];
            g_piv[2 * MAX_F + f] = S[47];
            g_piv[3 * MAX_F + f] = S[7];
            g_piv[4 * MAX_F + f] = S[23];
            g_piv[5 * MAX_F + f] = S[39];
            g_piv[6 * MAX_F + f] = S[55];
        }
        return;
    }

    // ---- detection block ----
    __shared__ int s_k32, s_f32, s_bad;
    if (threadIdx.x == 0) { s_k32 = 0; s_f32 = 0; s_bad = 0; }
    __syncthreads();
    // int64 little-endian small nonneg values => odd u32 words all zero.
    int lk = 0, lf = 0;
    int nk = min(nnz, 1024);
    for (int i = threadIdx.x; i < nk; i += blockDim.x)
        if (keys[2 * i + 1] != 0u) lk = 1;
    int nf = min(F, 1024);
    for (int i = threadIdx.x; i < nf; i += blockDim.x)
        if (fid[2 * i + 1] != 0u) lf = 1;
    if (lk) atomicOr(&s_k32, 1);
    if (lf) atomicOr(&s_f32, 1);
    __syncthreads();
    int f64 = !s_f32;
    int bad = 0;
    if (f64) {
        const long long* p = (const long long*)fid;
        for (int i = threadIdx.x; i < F; i += blockDim.x)
            if (p[i] != (long long)i) bad = 1;
    } else {
        const int* p = (const int*)fid;
        for (int i = threadIdx.x; i < F; i += blockDim.x)
            if (p[i] != i) bad = 1;
    }
    if (bad) atomicOr(&s_bad, 1);
    __syncthreads();
    if (threadIdx.x == 0) {
        g_k64 = !s_k32;
        g_f64 = f64;
        g_arange = !s_bad;
    }
}

// Calibrated descent: 3 pivot levels from smem, 32B chunk from gmem (L2).
__device__ __forceinline__ void descend(const float* __restrict__ s_piv,
                                        int fx, float v, long long key,
                                        unsigned& okey, float& oval) {
    float p0 = s_piv[fx];                                   // S31
    int b0 = p0 < v;
    float p1 = s_piv[(1 + b0) * MAX_F + fx];                // S15 / S47
    int b1 = p1 < v;
    float p2 = s_piv[(3 + ((b0 << 1) | b1)) * MAX_F + fx];  // S7/S23/S39/S55
    int b2 = p2 < v;
    int p = (b0 << 2) | (b1 << 1) | b2;
    const float4* rp = g_row + fx * 16 + 2 * p;
    float4 c0 = __ldg(rp);
    float4 c1 = __ldg(rp + 1);
    int bin = (p << 3)
            + (c0.x < v) + (c0.y < v) + (c0.z < v) + (c0.w < v)
            + (c1.x < v) + (c1.y < v) + (c1.z < v) + (c1.w < v);
    unsigned h = ((unsigned)(unsigned long long)key * GOLDEN
                  + (unsigned)bin) * GOLDEN;
    okey = h & OUT_MASK;
    oval = 1.0f;
}

__device__ __forceinline__ void process_fast(const float* __restrict__ s_piv,
                                             long long key, float v, int F,
                                             unsigned& okey, float& oval) {
    if ((unsigned long long)key < (unsigned long long)F) {
        descend(s_piv, (int)key, v, key, okey, oval);
    } else {
        okey = (unsigned)(unsigned long long)key & OUT_MASK;
        oval = v;
    }
}

// Generic: searchsorted(feature_ids, key, 'left') in gmem, then smem descent.
__device__ __forceinline__ void process_generic(const float* __restrict__ s_piv,
                                                long long key, float v,
                                                const void* fid_, int F,
                                                unsigned& okey, float& oval) {
    int lo = 0, hi = F, fx;
    bool cal;
    if (g_f64) {
        const long long* fid = (const long long*)fid_;
        while (lo < hi) {
            int mid = (lo + hi) >> 1;
            if (__ldg(fid + mid) < key) lo = mid + 1; else hi = mid;
        }
        fx = min(lo, F - 1);
        cal = (__ldg(fid + fx) == key);
    } else {
        const int* fid = (const int*)fid_;
        int k32 = (int)key;
        while (lo < hi) {
            int mid = (lo + hi) >> 1;
            if (__ldg(fid + mid) < k32) lo = mid + 1; else hi = mid;
        }
        fx = min(lo, F - 1);
        cal = (__ldg(fid + fx) == k32);
    }
    if (cal) descend(s_piv, fx, v, key, okey, oval);
    else {
        okey = (unsigned)(unsigned long long)key & OUT_MASK;
        oval = v;
    }
}

// Persistent hot kernel: 1 block/SM (224KB smem), grid-stride, 4 elems/group.
__global__ __launch_bounds__(1024, 1)
void hot_kernel(const void* __restrict__ keys_,
                const float* __restrict__ vals,
                const void* __restrict__ fid_,
                float* __restrict__ out,
                int nnz, int F) {
    extern __shared__ float s_piv[];
    for (int i = threadIdx.x; i < PIV_FLOATS; i += blockDim.x)
        s_piv[i] = __ldg(&g_piv[i]);
    __syncthreads();

    int arange = g_arange;
    int k64 = g_k64;
    int tid = blockIdx.x * blockDim.x + threadIdx.x;
    int nthreads = gridDim.x * blockDim.x;
    int nvec = nnz >> 2;  // full groups of 4

    for (int t = tid; t < nvec; t += nthreads) {
        int base = t * 4;
        long long k[4];
        float v[4];
        if (k64) {
            const longlong2* kp = (const longlong2*)keys_ + t * 2;
            longlong2 a = __ldcs(kp), b = __ldcs(kp + 1);
            k[0] = a.x; k[1] = a.y; k[2] = b.x; k[3] = b.y;
        } else {
            int4 a = __ldcs((const int4*)keys_ + t);
            k[0] = a.x; k[1] = a.y; k[2] = a.z; k[3] = a.w;
        }
        float4 vv = __ldcs((const float4*)vals + t);
        v[0] = vv.x; v[1] = vv.y; v[2] = vv.z; v[3] = vv.w;

        unsigned ok[4]; float ov[4];
        if (arange) {
#pragma unroll
            for (int j = 0; j < 4; j++)
                process_fast(s_piv, k[j], v[j], F, ok[j], ov[j]);
        } else {
#pragma unroll
            for (int j = 0; j < 4; j++)
                process_generic(s_piv, k[j], v[j], fid_, F, ok[j], ov[j]);
        }

        float4 fo = make_float4((float)ok[0], (float)ok[1],
                                (float)ok[2], (float)ok[3]);
        float4 vo = make_float4(ov[0], ov[1], ov[2], ov[3]);
        __stcs((float4*)(out + base), fo);
        __stcs((float4*)(out + nnz + base), vo);
    }

    // tail (nnz not divisible by 4)
    int tail_base = nvec * 4;
    for (int i = tail_base + tid; i < nnz; i += nthreads) {
        long long key = k64 ? ((const long long*)keys_)[i]
                            : (long long)((const int*)keys_)[i];
        float vj = vals[i];
        unsigned ok; float ov;
        if (arange) process_fast(s_piv, key, vj, F, ok, ov);
        else        process_generic(s_piv, key, vj, fid_, F, ok, ov);
        out[i] = (float)ok;
        out[nnz + i] = ov;
    }
}

extern "C" void kernel_launch(void* const* d_in, const int* in_sizes, int n_in,
                              void* d_out, int out_size) {
    const void* keys  = d_in[0];
    const float* vals = (const float*)d_in[1];
    const void* fid   = d_in[2];
    const float* bins = (const float*)d_in[3];
    int nnz = in_sizes[0];
    int F   = in_sizes[2];

    int nb_build = (F + FEAT_PER_BLOCK - 1) / FEAT_PER_BLOCK;  // 2048
    prep_kernel<<<nb_build + 1, 256>>>(bins, (const unsigned*)keys,
                                       (const unsigned*)fid, nnz, F, nb_build);

    static int nsm = 0;
    if (nsm == 0) {
        cudaDeviceGetAttribute(&nsm, cudaDevAttrMultiProcessorCount, 0);
        if (nsm <= 0) nsm = 148;
        cudaFuncSetAttribute(hot_kernel,
                             cudaFuncAttributeMaxDynamicSharedMemorySize,
                             SMEM_BYTES);
    }
    hot_kernel<<<nsm, 1024, SMEM_BYTES>>>(keys, vals, fid, (float*)d_out,
                                          nnz, F);
}